// round 9
// baseline (speedup 1.0000x reference)
#include <cuda_runtime.h>
#include <cuda_bf16.h>
#include <math.h>
#include <cstdint>

// ContrastiveLoss N=8192 D=128 temp=0.05 — plain-bf16 HMMA, symmetric tiles,
// y fused into the tile kernel (ballot -> bits -> in-tile prefix ranks).
// loss = -mean_i [ (1/ppn_i) * sum_{j: y_ij=1} log( e_ij / (e_ij + nl_i) ) ]
// log(e/(e+nl)) = -log1p(nl*exp(-t)), t = cos/T.

#define NN 8192
#define DD 128
#define INV_T 20.0f
#define NSLOT 192            // nl partial slots: row-role 0..127, col-role 128..191
#define BLK_POS 32           // positive slots per (row, 128-col block)
#define POS_STRIDE 2048      // 64 blocks * 32

__device__ __nv_bfloat16 g_xhi[NN * DD];
__device__ float g_nl_part[(size_t)NN * NSLOT];
__device__ int   g_bcnt[(size_t)NN * 64];
__device__ float g_pos[(size_t)NN * POS_STRIDE];
__device__ float g_lm[NN];

// ---------------------------------------------------------------------------
__device__ __forceinline__ uint32_t smem_u32(const void* p) {
    uint32_t a;
    asm("{ .reg .u64 t; cvta.to.shared.u64 t, %1; cvt.u32.u64 %0, t; }" : "=r"(a) : "l"(p));
    return a;
}
__device__ __forceinline__ void ldmx4(uint32_t* r, uint32_t addr) {
    asm volatile("ldmatrix.sync.aligned.m8n8.x4.shared.b16 {%0,%1,%2,%3}, [%4];"
        : "=r"(r[0]), "=r"(r[1]), "=r"(r[2]), "=r"(r[3]) : "r"(addr));
}
__device__ __forceinline__ void mma_bf16(float* d, const uint32_t* a,
                                         uint32_t b0, uint32_t b1) {
    asm volatile("mma.sync.aligned.m16n8k16.row.col.f32.bf16.bf16.f32 "
        "{%0,%1,%2,%3}, {%4,%5,%6,%7}, {%8,%9}, {%0,%1,%2,%3};"
        : "+f"(d[0]), "+f"(d[1]), "+f"(d[2]), "+f"(d[3])
        : "r"(a[0]), "r"(a[1]), "r"(a[2]), "r"(a[3]), "r"(b0), "r"(b1));
}

// ---------------------------------------------------------------------------
__global__ void k_normalize(const float* __restrict__ x) {
    int row  = blockIdx.x * 8 + (threadIdx.x >> 5);
    int lane = threadIdx.x & 31;
    float4 v = ((const float4*)(x + (size_t)row * DD))[lane];
    float ss = v.x * v.x + v.y * v.y + v.z * v.z + v.w * v.w;
    #pragma unroll
    for (int o = 16; o; o >>= 1) ss += __shfl_xor_sync(0xFFFFFFFFu, ss, o);
    float inv = rsqrtf(ss);
    float f[4] = {v.x * inv, v.y * inv, v.z * inv, v.w * inv};
    ushort4 hi4;
    unsigned short* hp = &hi4.x;
    #pragma unroll
    for (int i = 0; i < 4; i++) {
        __nv_bfloat16 h = __float2bfloat16(f[i]);
        hp[i] = *(unsigned short*)&h;
    }
    ((ushort4*)(g_xhi + (size_t)row * DD))[lane] = hi4;
}

// ---------------------------------------------------------------------------
__global__ void k_pad() {}   // keeps k_tile at launch index 3 (ncu capture slot)

// ---------------------------------------------------------------------------
// HMMA tile GEMM + fused y-ballot + dual-role epilogue. Triangular grid.
// SMEM: A@0 (32K), B@32768 (32K), yb@65536, pf@67584, yb2@69632, pf2@71680.
// Colred scratch reuses A region ([32][132] floats) after the mainloop.
#define SM_A   0
#define SM_B   32768
#define SM_YB  65536
#define SM_PF  67584
#define SM_YB2 69632
#define SM_PF2 71680
#define SM_TOT 73728
#define NBLK   2080          // 64*65/2

__global__ void __launch_bounds__(256, 2) k_tile(const float* __restrict__ y) {
    int bi = 0, rem = blockIdx.x;
    while (rem >= 64 - bi) { rem -= 64 - bi; bi++; }
    const int bj = bi + rem;
    const bool offdiag = (bi != bj);

    extern __shared__ char smem[];
    uint32_t sbase = smem_u32(smem);
    const int tid  = threadIdx.x;
    const int wid  = tid >> 5;
    const int lane = tid & 31;
    const int warp_m = wid >> 1;
    const int warp_n = wid & 1;
    const int row0 = bi * 128;
    const int col0 = bj * 128;

    unsigned* yb  = (unsigned*)(smem + SM_YB);
    int*      pf  = (int*)(smem + SM_PF);
    unsigned* yb2 = (unsigned*)(smem + SM_YB2);
    int*      pf2 = (int*)(smem + SM_PF2);

    // ---- load A/B tiles (L2-resident bf16)
    {
        const uint4* ah = (const uint4*)(g_xhi + (size_t)row0 * DD);
        const uint4* bh = (const uint4*)(g_xhi + (size_t)col0 * DD);
        #pragma unroll
        for (int i = 0; i < 8; i++) {
            int idx = tid + i * 256;
            int r   = idx >> 4;
            int c   = idx & 15;
            uint32_t so = (uint32_t)r * 256 + (uint32_t)((c ^ (r & 7)) * 16);
            *(uint4*)(smem + SM_A + so) = ah[idx];
            *(uint4*)(smem + SM_B + so) = bh[idx];
        }
    }

    // ---- y ballots: warp w handles rows w*16..w*16+15, 4 words each
    {
        #pragma unroll 4
        for (int i = 0; i < 16; i++) {
            int r = wid * 16 + (i >> 2);
            int w = i & 3;
            float v = y[(size_t)(row0 + r) * NN + col0 + w * 32 + lane];
            unsigned word = __ballot_sync(0xFFFFFFFFu, v != 0.0f);
            if (lane == 0) yb[r * 4 + w] = word;
            if (offdiag) {
                float v2 = y[(size_t)(col0 + r) * NN + row0 + w * 32 + lane];
                unsigned word2 = __ballot_sync(0xFFFFFFFFu, v2 != 0.0f);
                if (lane == 0) yb2[r * 4 + w] = word2;
            }
        }
        #pragma unroll 4
        for (int i = 16; i < 64; i++) {
            int r = wid * 16 + (i >> 2);
            int w = i & 3;
            float v = y[(size_t)(row0 + r) * NN + col0 + w * 32 + lane];
            unsigned word = __ballot_sync(0xFFFFFFFFu, v != 0.0f);
            if (lane == 0) yb[r * 4 + w] = word;
            if (offdiag) {
                float v2 = y[(size_t)(col0 + r) * NN + row0 + w * 32 + lane];
                unsigned word2 = __ballot_sync(0xFFFFFFFFu, v2 != 0.0f);
                if (lane == 0) yb2[r * 4 + w] = word2;
            }
        }
    }
    __syncthreads();

    // ---- within-segment prefixes + per-(row,block) counts
    if (tid < 128) {
        int r = tid;
        unsigned w0 = yb[r * 4], w1 = yb[r * 4 + 1], w2 = yb[r * 4 + 2], w3 = yb[r * 4 + 3];
        int c0 = __popc(w0), c1 = __popc(w1), c2 = __popc(w2), c3 = __popc(w3);
        pf[r * 4] = 0; pf[r * 4 + 1] = c0; pf[r * 4 + 2] = c0 + c1; pf[r * 4 + 3] = c0 + c1 + c2;
        g_bcnt[(size_t)(row0 + r) * 64 + bj] = c0 + c1 + c2 + c3;
    } else if (offdiag) {
        int c = tid - 128;
        unsigned w0 = yb2[c * 4], w1 = yb2[c * 4 + 1], w2 = yb2[c * 4 + 2], w3 = yb2[c * 4 + 3];
        int c0 = __popc(w0), c1 = __popc(w1), c2 = __popc(w2), c3 = __popc(w3);
        pf2[c * 4] = 0; pf2[c * 4 + 1] = c0; pf2[c * 4 + 2] = c0 + c1; pf2[c * 4 + 3] = c0 + c1 + c2;
        g_bcnt[(size_t)(col0 + c) * 64 + bi] = c0 + c1 + c2 + c3;
    }
    __syncthreads();

    // ---- mainloop
    float acc[2][8][4];
    #pragma unroll
    for (int i = 0; i < 2; i++)
        #pragma unroll
        for (int j = 0; j < 8; j++)
            #pragma unroll
            for (int q = 0; q < 4; q++) acc[i][j][q] = 0.0f;

    const uint32_t lane_row = lane & 15;
    const uint32_t kb  = lane >> 4;
    const uint32_t key = lane & 7;
    const uint32_t a_base = sbase + SM_A + (warp_m * 32 + lane_row) * 256;
    const uint32_t b_base = sbase + SM_B + (warp_n * 64 + lane_row) * 256;

    #pragma unroll
    for (int k16 = 0; k16 < 8; k16++) {
        uint32_t ca = (((uint32_t)k16 * 2 + kb) ^ key) * 16;
        uint32_t a0[4], a1[4];
        ldmx4(a0, a_base + ca);
        ldmx4(a1, a_base + 4096 + ca);
        #pragma unroll
        for (int n16 = 0; n16 < 4; n16++) {
            uint32_t bf[4];
            ldmx4(bf, b_base + n16 * 4096 + ca);
            mma_bf16(acc[0][n16 * 2 + 0], a0, bf[0], bf[2]);
            mma_bf16(acc[0][n16 * 2 + 1], a0, bf[1], bf[3]);
            mma_bf16(acc[1][n16 * 2 + 0], a1, bf[0], bf[2]);
            mma_bf16(acc[1][n16 * 2 + 1], a1, bf[1], bf[3]);
        }
    }
    __syncthreads();   // A/B smem dead; colred scratch takes over

    // ---- dual-role epilogue
    float* cr = (float*)(smem + SM_A);   // [32][132]
    const int qm = lane >> 2;
    const int qn = (lane & 3) * 2;
    const int g  = warp_m * 8 + qm;
    float negLo[2] = {0.f, 0.f};
    float negHi[2] = {0.f, 0.f};

    #pragma unroll
    for (int n8 = 0; n8 < 8; n8++) {
        const int half = n8 >> 2;
        const int w = warp_n * 2 + half;
        const int p = (n8 & 3) * 8 + qn;
        const unsigned m0 = 1u << p, m1 = m0 << 1;
        const int clA = warp_n * 64 + n8 * 8 + qn;
        unsigned w2c0 = 0, w2c1 = 0;
        int pf2c0 = 0, pf2c1 = 0;
        if (offdiag) {
            w2c0 = yb2[clA * 4 + warp_m];       pf2c0 = pf2[clA * 4 + warp_m];
            w2c1 = yb2[(clA + 1) * 4 + warp_m]; pf2c1 = pf2[(clA + 1) * 4 + warp_m];
        }
        float negc0 = 0.0f, negc1 = 0.0f;
        #pragma unroll
        for (int m_i = 0; m_i < 2; m_i++) {
            const int rlo = warp_m * 32 + m_i * 16 + qm;
            const int rhi = rlo + 8;
            const unsigned wordL = yb[rlo * 4 + w];
            const unsigned wordH = yb[rhi * 4 + w];
            const int prefL = pf[rlo * 4 + w];
            const int prefH = pf[rhi * 4 + w];
            const float* d = acc[m_i][n8];
            float t0 = d[0] * INV_T, t1 = d[1] * INV_T;
            float t2 = d[2] * INV_T, t3 = d[3] * INV_T;
            float e0 = __expf(t0), e1 = __expf(t1);
            float e2 = __expf(t2), e3 = __expf(t3);
            negLo[m_i] += (wordL & m0) ? 0.0f : e0;
            negLo[m_i] += (wordL & m1) ? 0.0f : e1;
            negHi[m_i] += (wordH & m0) ? 0.0f : e2;
            negHi[m_i] += (wordH & m1) ? 0.0f : e3;
            float* gposL = g_pos + (size_t)(row0 + rlo) * POS_STRIDE + bj * BLK_POS;
            float* gposH = g_pos + (size_t)(row0 + rhi) * POS_STRIDE + bj * BLK_POS;
            if (wordL & m0) gposL[prefL + __popc(wordL & (m0 - 1))] = t0;
            if (wordL & m1) gposL[prefL + __popc(wordL & (m1 - 1))] = t1;
            if (wordH & m0) gposH[prefH + __popc(wordH & (m0 - 1))] = t2;
            if (wordH & m1) gposH[prefH + __popc(wordH & (m1 - 1))] = t3;
            if (offdiag) {
                const unsigned bL = 1u << (rlo & 31);
                const unsigned bH = 1u << (rhi & 31);
                negc0 += (w2c0 & bL) ? 0.0f : e0;
                negc0 += (w2c0 & bH) ? 0.0f : e2;
                negc1 += (w2c1 & bL) ? 0.0f : e1;
                negc1 += (w2c1 & bH) ? 0.0f : e3;
                float* gpc0 = g_pos + (size_t)(col0 + clA) * POS_STRIDE + bi * BLK_POS;
                float* gpc1 = g_pos + (size_t)(col0 + clA + 1) * POS_STRIDE + bi * BLK_POS;
                if (w2c0 & bL) gpc0[pf2c0 + __popc(w2c0 & (bL - 1))] = t0;
                if (w2c0 & bH) gpc0[pf2c0 + __popc(w2c0 & (bH - 1))] = t2;
                if (w2c1 & bL) gpc1[pf2c1 + __popc(w2c1 & (bL - 1))] = t1;
                if (w2c1 & bH) gpc1[pf2c1 + __popc(w2c1 & (bH - 1))] = t3;
            }
        }
        if (offdiag) {
            cr[g * 132 + clA]     = negc0;
            cr[g * 132 + clA + 1] = negc1;
        }
    }

    // row-role nl partials
    int slotR = bj * 2 + warp_n;
    #pragma unroll
    for (int m_i = 0; m_i < 2; m_i++) {
        float vlo = negLo[m_i], vhi = negHi[m_i];
        vlo += __shfl_xor_sync(0xFFFFFFFFu, vlo, 1);
        vlo += __shfl_xor_sync(0xFFFFFFFFu, vlo, 2);
        vhi += __shfl_xor_sync(0xFFFFFFFFu, vhi, 1);
        vhi += __shfl_xor_sync(0xFFFFFFFFu, vhi, 2);
        if ((lane & 3) == 0) {
            int r = row0 + warp_m * 32 + m_i * 16 + qm;
            g_nl_part[(size_t)r * NSLOT + slotR]       = vlo;
            g_nl_part[(size_t)(r + 8) * NSLOT + slotR] = vhi;
        }
    }

    // col-role nl reduce
    __syncthreads();
    if (offdiag && tid < 128) {
        float s = 0.0f;
        #pragma unroll
        for (int gg = 0; gg < 32; gg++) s += cr[gg * 132 + tid];
        g_nl_part[(size_t)(col0 + tid) * NSLOT + 128 + bi] = s;
    }
}

// ---------------------------------------------------------------------------
// Per-row loss. nl slots: [2br,128) U [128,128+br). Positives via g_bcnt/g_pos.
__global__ void k_rowloss() {
    int row  = blockIdx.x * 8 + (threadIdx.x >> 5);
    int lane = threadIdx.x & 31;
    int br = row >> 7;
    const float* p = g_nl_part + (size_t)row * NSLOT;
    int lenR = 128 - 2 * br;
    int lenT = lenR + br;
    float nl = 0.0f;
    for (int i = lane; i < lenT; i += 32) {
        int s = (i < lenR) ? (2 * br + i) : (128 + (i - lenR));
        nl += p[s];
    }
    #pragma unroll
    for (int o = 16; o; o >>= 1) nl += __shfl_xor_sync(0xFFFFFFFFu, nl, o);

    const int* bc = g_bcnt + (size_t)row * 64;
    const float* ps = g_pos + (size_t)row * POS_STRIDE;
    float acc = 0.0f;
    int cnt = 0;
    #pragma unroll
    for (int bb = 0; bb < 2; bb++) {
        int b = lane + bb * 32;
        int c = bc[b];
        cnt += c;
        const float* pp = ps + b * BLK_POS;
        for (int k = 0; k < c; k++)
            acc += log1pf(nl * __expf(-pp[k]));
    }
    #pragma unroll
    for (int o = 16; o; o >>= 1) {
        acc += __shfl_xor_sync(0xFFFFFFFFu, acc, o);
        cnt += __shfl_xor_sync(0xFFFFFFFFu, cnt, o);
    }
    if (lane == 0) g_lm[row] = acc / (float)cnt;
}

// ---------------------------------------------------------------------------
__global__ void k_final(float* __restrict__ out) {
    __shared__ float sm[256];
    float s = 0.0f;
    for (int i = threadIdx.x; i < NN; i += 256) s += g_lm[i];
    sm[threadIdx.x] = s;
    __syncthreads();
    for (int o = 128; o; o >>= 1) {
        if (threadIdx.x < o) sm[threadIdx.x] += sm[threadIdx.x + o];
        __syncthreads();
    }
    if (threadIdx.x == 0) out[0] = sm[0] / (float)NN;
}

// ---------------------------------------------------------------------------
extern "C" void kernel_launch(void* const* d_in, const int* in_sizes, int n_in,
                              void* d_out, int out_size) {
    const float* x = (const float*)d_in[0];
    const float* y = (const float*)d_in[1];

    cudaFuncSetAttribute(k_tile, cudaFuncAttributeMaxDynamicSharedMemorySize, SM_TOT);

    k_normalize<<<NN / 8, 256>>>(x);                     // idx 0
    k_pad<<<1, 32>>>();                                  // idx 1
    k_pad<<<1, 32>>>();                                  // idx 2
    k_tile<<<NBLK, 256, SM_TOT>>>(y);                    // idx 3 (ncu slot)
    k_rowloss<<<NN / 8, 256>>>();                        // idx 4
    k_final<<<1, 256>>>((float*)d_out);                  // idx 5
}

// round 10
// speedup vs baseline: 2.3737x; 2.3737x over previous
#include <cuda_runtime.h>
#include <cuda_bf16.h>
#include <math.h>
#include <cstdint>

// ContrastiveLoss N=8192 D=128 temp=0.05 — plain-bf16 HMMA, symmetric tiles,
// y fused into the tile kernel with high-MLP float4 loads (no ballots).
// loss = -mean_i [ (1/ppn_i) * sum_{j: y_ij=1} log( e_ij / (e_ij + nl_i) ) ]
// log(e/(e+nl)) = -log1p(nl*exp(-t)), t = cos/T.

#define NN 8192
#define DD 128
#define INV_T 20.0f
#define NSLOT 192            // nl partial slots: row-role 0..127, col-role 128..191
#define BLK_POS 32           // positive slots per (row, 128-col block)
#define POS_STRIDE 2048      // 64 blocks * 32

__device__ __nv_bfloat16 g_xhi[NN * DD];
__device__ float g_nl_part[(size_t)NN * NSLOT];
__device__ int   g_bcnt[(size_t)NN * 64];
__device__ float g_pos[(size_t)NN * POS_STRIDE];
__device__ float g_lm[NN];

// ---------------------------------------------------------------------------
__device__ __forceinline__ uint32_t smem_u32(const void* p) {
    uint32_t a;
    asm("{ .reg .u64 t; cvta.to.shared.u64 t, %1; cvt.u32.u64 %0, t; }" : "=r"(a) : "l"(p));
    return a;
}
__device__ __forceinline__ void ldmx4(uint32_t* r, uint32_t addr) {
    asm volatile("ldmatrix.sync.aligned.m8n8.x4.shared.b16 {%0,%1,%2,%3}, [%4];"
        : "=r"(r[0]), "=r"(r[1]), "=r"(r[2]), "=r"(r[3]) : "r"(addr));
}
__device__ __forceinline__ void mma_bf16(float* d, const uint32_t* a,
                                         uint32_t b0, uint32_t b1) {
    asm volatile("mma.sync.aligned.m16n8k16.row.col.f32.bf16.bf16.f32 "
        "{%0,%1,%2,%3}, {%4,%5,%6,%7}, {%8,%9}, {%0,%1,%2,%3};"
        : "+f"(d[0]), "+f"(d[1]), "+f"(d[2]), "+f"(d[3])
        : "r"(a[0]), "r"(a[1]), "r"(a[2]), "r"(a[3]), "r"(b0), "r"(b1));
}
__device__ __forceinline__ unsigned nib4(float4 v) {
    return (unsigned)(v.x != 0.0f) | ((unsigned)(v.y != 0.0f) << 1)
         | ((unsigned)(v.z != 0.0f) << 2) | ((unsigned)(v.w != 0.0f) << 3);
}

// ---------------------------------------------------------------------------
__global__ void k_normalize(const float* __restrict__ x) {
    int row  = blockIdx.x * 8 + (threadIdx.x >> 5);
    int lane = threadIdx.x & 31;
    float4 v = ((const float4*)(x + (size_t)row * DD))[lane];
    float ss = v.x * v.x + v.y * v.y + v.z * v.z + v.w * v.w;
    #pragma unroll
    for (int o = 16; o; o >>= 1) ss += __shfl_xor_sync(0xFFFFFFFFu, ss, o);
    float inv = rsqrtf(ss);
    float f[4] = {v.x * inv, v.y * inv, v.z * inv, v.w * inv};
    ushort4 hi4;
    unsigned short* hp = &hi4.x;
    #pragma unroll
    for (int i = 0; i < 4; i++) {
        __nv_bfloat16 h = __float2bfloat16(f[i]);
        hp[i] = *(unsigned short*)&h;
    }
    ((ushort4*)(g_xhi + (size_t)row * DD))[lane] = hi4;
}

// ---------------------------------------------------------------------------
__global__ void k_pad() {}   // keeps k_tile at launch index 3 (ncu capture slot)

// ---------------------------------------------------------------------------
// HMMA tile GEMM + fused high-MLP y load + dual-role epilogue. Triangular grid.
#define SM_A   0
#define SM_B   32768
#define SM_YB  65536
#define SM_PF  67584
#define SM_YB2 69632
#define SM_PF2 71680
#define SM_TOT 73728
#define NBLK   2080          // 64*65/2

__global__ void __launch_bounds__(256, 2) k_tile(const float* __restrict__ y) {
    int bi = 0, rem = blockIdx.x;
    while (rem >= 64 - bi) { rem -= 64 - bi; bi++; }
    const int bj = bi + rem;
    const bool offdiag = (bi != bj);

    extern __shared__ char smem[];
    uint32_t sbase = smem_u32(smem);
    const int tid  = threadIdx.x;
    const int wid  = tid >> 5;
    const int lane = tid & 31;
    const int warp_m = wid >> 1;
    const int warp_n = wid & 1;
    const int row0 = bi * 128;
    const int col0 = bj * 128;

    unsigned* yb  = (unsigned*)(smem + SM_YB);
    int*      pf  = (int*)(smem + SM_PF);
    unsigned* yb2 = (unsigned*)(smem + SM_YB2);
    int*      pf2 = (int*)(smem + SM_PF2);

    // ---- load A/B tiles (L2-resident bf16)
    {
        const uint4* ah = (const uint4*)(g_xhi + (size_t)row0 * DD);
        const uint4* bh = (const uint4*)(g_xhi + (size_t)col0 * DD);
        #pragma unroll
        for (int i = 0; i < 8; i++) {
            int idx = tid + i * 256;
            int r   = idx >> 4;
            int c   = idx & 15;
            uint32_t so = (uint32_t)r * 256 + (uint32_t)((c ^ (r & 7)) * 16);
            *(uint4*)(smem + SM_A + so) = ah[idx];
            *(uint4*)(smem + SM_B + so) = bh[idx];
        }
    }

    // ---- y load, high MLP: 8 threads per row, 4 consecutive float4 each
    // thread covers cols [16*q8, 16*q8+16); pairs merge 16-bit halves via shfl.
    {
        const int q8 = tid & 7;
        #pragma unroll
        for (int p = 0; p < 4; p++) {
            int r = p * 32 + (tid >> 3);
            const float4* yr = (const float4*)(y + (size_t)(row0 + r) * NN + col0) + q8 * 4;
            unsigned m = 0;
            #pragma unroll
            for (int k = 0; k < 4; k++) m |= nib4(yr[k]) << (k * 4);
            unsigned o = __shfl_xor_sync(0xFFFFFFFFu, m, 1);
            if (!(tid & 1)) yb[r * 4 + (q8 >> 1)] = m | (o << 16);
            if (offdiag) {
                const float4* yc = (const float4*)(y + (size_t)(col0 + r) * NN + row0) + q8 * 4;
                unsigned m2 = 0;
                #pragma unroll
                for (int k = 0; k < 4; k++) m2 |= nib4(yc[k]) << (k * 4);
                unsigned o2 = __shfl_xor_sync(0xFFFFFFFFu, m2, 1);
                if (!(tid & 1)) yb2[r * 4 + (q8 >> 1)] = m2 | (o2 << 16);
            }
        }
    }
    __syncthreads();

    // ---- within-segment prefixes + per-(row,block) counts
    if (tid < 128) {
        int r = tid;
        unsigned w0 = yb[r * 4], w1 = yb[r * 4 + 1], w2 = yb[r * 4 + 2], w3 = yb[r * 4 + 3];
        int c0 = __popc(w0), c1 = __popc(w1), c2 = __popc(w2), c3 = __popc(w3);
        pf[r * 4] = 0; pf[r * 4 + 1] = c0; pf[r * 4 + 2] = c0 + c1; pf[r * 4 + 3] = c0 + c1 + c2;
        g_bcnt[(size_t)(row0 + r) * 64 + bj] = c0 + c1 + c2 + c3;
    } else if (offdiag) {
        int c = tid - 128;
        unsigned w0 = yb2[c * 4], w1 = yb2[c * 4 + 1], w2 = yb2[c * 4 + 2], w3 = yb2[c * 4 + 3];
        int c0 = __popc(w0), c1 = __popc(w1), c2 = __popc(w2), c3 = __popc(w3);
        pf2[c * 4] = 0; pf2[c * 4 + 1] = c0; pf2[c * 4 + 2] = c0 + c1; pf2[c * 4 + 3] = c0 + c1 + c2;
        g_bcnt[(size_t)(col0 + c) * 64 + bi] = c0 + c1 + c2 + c3;
    }
    __syncthreads();

    // ---- mainloop
    float acc[2][8][4];
    #pragma unroll
    for (int i = 0; i < 2; i++)
        #pragma unroll
        for (int j = 0; j < 8; j++)
            #pragma unroll
            for (int q = 0; q < 4; q++) acc[i][j][q] = 0.0f;

    const uint32_t lane_row = lane & 15;
    const uint32_t kb  = lane >> 4;
    const uint32_t key = lane & 7;
    const uint32_t a_base = sbase + SM_A + (warp_m * 32 + lane_row) * 256;
    const uint32_t b_base = sbase + SM_B + (warp_n * 64 + lane_row) * 256;

    #pragma unroll
    for (int k16 = 0; k16 < 8; k16++) {
        uint32_t ca = (((uint32_t)k16 * 2 + kb) ^ key) * 16;
        uint32_t a0[4], a1[4];
        ldmx4(a0, a_base + ca);
        ldmx4(a1, a_base + 4096 + ca);
        #pragma unroll
        for (int n16 = 0; n16 < 4; n16++) {
            uint32_t bf[4];
            ldmx4(bf, b_base + n16 * 4096 + ca);
            mma_bf16(acc[0][n16 * 2 + 0], a0, bf[0], bf[2]);
            mma_bf16(acc[0][n16 * 2 + 1], a0, bf[1], bf[3]);
            mma_bf16(acc[1][n16 * 2 + 0], a1, bf[0], bf[2]);
            mma_bf16(acc[1][n16 * 2 + 1], a1, bf[1], bf[3]);
        }
    }
    __syncthreads();   // A/B smem dead; colred scratch takes over

    // ---- dual-role epilogue
    float* cr = (float*)(smem + SM_A);   // [32][132]
    const int qm = lane >> 2;
    const int qn = (lane & 3) * 2;
    const int g  = warp_m * 8 + qm;
    float negLo[2] = {0.f, 0.f};
    float negHi[2] = {0.f, 0.f};

    #pragma unroll
    for (int n8 = 0; n8 < 8; n8++) {
        const int half = n8 >> 2;
        const int w = warp_n * 2 + half;
        const int p = (n8 & 3) * 8 + qn;
        const unsigned m0 = 1u << p, m1 = m0 << 1;
        const int clA = warp_n * 64 + n8 * 8 + qn;
        unsigned w2c0 = 0, w2c1 = 0;
        int pf2c0 = 0, pf2c1 = 0;
        if (offdiag) {
            w2c0 = yb2[clA * 4 + warp_m];       pf2c0 = pf2[clA * 4 + warp_m];
            w2c1 = yb2[(clA + 1) * 4 + warp_m]; pf2c1 = pf2[(clA + 1) * 4 + warp_m];
        }
        float negc0 = 0.0f, negc1 = 0.0f;
        #pragma unroll
        for (int m_i = 0; m_i < 2; m_i++) {
            const int rlo = warp_m * 32 + m_i * 16 + qm;
            const int rhi = rlo + 8;
            const unsigned wordL = yb[rlo * 4 + w];
            const unsigned wordH = yb[rhi * 4 + w];
            const int prefL = pf[rlo * 4 + w];
            const int prefH = pf[rhi * 4 + w];
            const float* d = acc[m_i][n8];
            float t0 = d[0] * INV_T, t1 = d[1] * INV_T;
            float t2 = d[2] * INV_T, t3 = d[3] * INV_T;
            float e0 = __expf(t0), e1 = __expf(t1);
            float e2 = __expf(t2), e3 = __expf(t3);
            negLo[m_i] += (wordL & m0) ? 0.0f : e0;
            negLo[m_i] += (wordL & m1) ? 0.0f : e1;
            negHi[m_i] += (wordH & m0) ? 0.0f : e2;
            negHi[m_i] += (wordH & m1) ? 0.0f : e3;
            float* gposL = g_pos + (size_t)(row0 + rlo) * POS_STRIDE + bj * BLK_POS;
            float* gposH = g_pos + (size_t)(row0 + rhi) * POS_STRIDE + bj * BLK_POS;
            if (wordL & m0) gposL[prefL + __popc(wordL & (m0 - 1))] = t0;
            if (wordL & m1) gposL[prefL + __popc(wordL & (m1 - 1))] = t1;
            if (wordH & m0) gposH[prefH + __popc(wordH & (m0 - 1))] = t2;
            if (wordH & m1) gposH[prefH + __popc(wordH & (m1 - 1))] = t3;
            if (offdiag) {
                const unsigned bL = 1u << (rlo & 31);
                const unsigned bH = 1u << (rhi & 31);
                negc0 += (w2c0 & bL) ? 0.0f : e0;
                negc0 += (w2c0 & bH) ? 0.0f : e2;
                negc1 += (w2c1 & bL) ? 0.0f : e1;
                negc1 += (w2c1 & bH) ? 0.0f : e3;
                float* gpc0 = g_pos + (size_t)(col0 + clA) * POS_STRIDE + bi * BLK_POS;
                float* gpc1 = g_pos + (size_t)(col0 + clA + 1) * POS_STRIDE + bi * BLK_POS;
                if (w2c0 & bL) gpc0[pf2c0 + __popc(w2c0 & (bL - 1))] = t0;
                if (w2c0 & bH) gpc0[pf2c0 + __popc(w2c0 & (bH - 1))] = t2;
                if (w2c1 & bL) gpc1[pf2c1 + __popc(w2c1 & (bL - 1))] = t1;
                if (w2c1 & bH) gpc1[pf2c1 + __popc(w2c1 & (bH - 1))] = t3;
            }
        }
        if (offdiag) {
            cr[g * 132 + clA]     = negc0;
            cr[g * 132 + clA + 1] = negc1;
        }
    }

    // row-role nl partials
    int slotR = bj * 2 + warp_n;
    #pragma unroll
    for (int m_i = 0; m_i < 2; m_i++) {
        float vlo = negLo[m_i], vhi = negHi[m_i];
        vlo += __shfl_xor_sync(0xFFFFFFFFu, vlo, 1);
        vlo += __shfl_xor_sync(0xFFFFFFFFu, vlo, 2);
        vhi += __shfl_xor_sync(0xFFFFFFFFu, vhi, 1);
        vhi += __shfl_xor_sync(0xFFFFFFFFu, vhi, 2);
        if ((lane & 3) == 0) {
            int r = row0 + warp_m * 32 + m_i * 16 + qm;
            g_nl_part[(size_t)r * NSLOT + slotR]       = vlo;
            g_nl_part[(size_t)(r + 8) * NSLOT + slotR] = vhi;
        }
    }

    // col-role nl reduce
    __syncthreads();
    if (offdiag && tid < 128) {
        float s = 0.0f;
        #pragma unroll
        for (int gg = 0; gg < 32; gg++) s += cr[gg * 132 + tid];
        g_nl_part[(size_t)(col0 + tid) * NSLOT + 128 + bi] = s;
    }
}

// ---------------------------------------------------------------------------
// Per-row loss. nl slots: [2br,128) U [128,128+br). Positives via g_bcnt/g_pos.
__global__ void k_rowloss() {
    int row  = blockIdx.x * 8 + (threadIdx.x >> 5);
    int lane = threadIdx.x & 31;
    int br = row >> 7;
    const float* p = g_nl_part + (size_t)row * NSLOT;
    int lenR = 128 - 2 * br;
    int lenT = lenR + br;
    float nl = 0.0f;
    for (int i = lane; i < lenT; i += 32) {
        int s = (i < lenR) ? (2 * br + i) : (128 + (i - lenR));
        nl += p[s];
    }
    #pragma unroll
    for (int o = 16; o; o >>= 1) nl += __shfl_xor_sync(0xFFFFFFFFu, nl, o);

    const int* bc = g_bcnt + (size_t)row * 64;
    const float* ps = g_pos + (size_t)row * POS_STRIDE;
    float acc = 0.0f;
    int cnt = 0;
    #pragma unroll
    for (int bb = 0; bb < 2; bb++) {
        int b = lane + bb * 32;
        int c = bc[b];
        cnt += c;
        const float* pp = ps + b * BLK_POS;
        for (int k = 0; k < c; k++)
            acc += log1pf(nl * __expf(-pp[k]));
    }
    #pragma unroll
    for (int o = 16; o; o >>= 1) {
        acc += __shfl_xor_sync(0xFFFFFFFFu, acc, o);
        cnt += __shfl_xor_sync(0xFFFFFFFFu, cnt, o);
    }
    if (lane == 0) g_lm[row] = acc / (float)cnt;
}

// ---------------------------------------------------------------------------
__global__ void k_final(float* __restrict__ out) {
    __shared__ float sm[256];
    float s = 0.0f;
    for (int i = threadIdx.x; i < NN; i += 256) s += g_lm[i];
    sm[threadIdx.x] = s;
    __syncthreads();
    for (int o = 128; o; o >>= 1) {
        if (threadIdx.x < o) sm[threadIdx.x] += sm[threadIdx.x + o];
        __syncthreads();
    }
    if (threadIdx.x == 0) out[0] = sm[0] / (float)NN;
}

// ---------------------------------------------------------------------------
extern "C" void kernel_launch(void* const* d_in, const int* in_sizes, int n_in,
                              void* d_out, int out_size) {
    const float* x = (const float*)d_in[0];
    const float* y = (const float*)d_in[1];

    cudaFuncSetAttribute(k_tile, cudaFuncAttributeMaxDynamicSharedMemorySize, SM_TOT);

    k_normalize<<<NN / 8, 256>>>(x);                     // idx 0
    k_pad<<<1, 32>>>();                                  // idx 1
    k_pad<<<1, 32>>>();                                  // idx 2
    k_tile<<<NBLK, 256, SM_TOT>>>(y);                    // idx 3 (ncu slot)
    k_rowloss<<<NN / 8, 256>>>();                        // idx 4
    k_final<<<1, 256>>>((float*)d_out);                  // idx 5
}